// round 1
// baseline (speedup 1.0000x reference)
#include <cuda_runtime.h>
#include <math.h>

// Problem constants
#define BB  4
#define SS  2048
#define DD  1024
#define HH  16
#define DKK 64
#define MM  (BB*SS)   // 8192 total rows

// Static device scratch (allowed; no dynamic allocation)
__device__ float g_Q[(size_t)BB*HH*SS*DKK];   // 32 MB, [B,H,S,DK]
__device__ float g_K[(size_t)BB*HH*SS*DKK];   // 32 MB
__device__ float g_V[(size_t)BB*HH*SS*DKK];   // 32 MB
__device__ float g_AO[(size_t)BB*SS*DD];      // 32 MB, concat layout [B,S,D]

// ---------------------------------------------------------------------------
// Per-head projection GEMM: OUT[b,h,s,k] = sum_d X[b,s,d] * W[h,d,k] + bias[h,k]
// Tile: BM=128, BN=64(=DK), BK=32. 256 threads, each computes 8x4 outputs.
// WHICH selects destination: 0->g_Q, 1->g_K, 2->g_V
// ---------------------------------------------------------------------------
template<int WHICH>
__global__ __launch_bounds__(256)
void proj_head_kernel(const float* __restrict__ X,
                      const float* __restrict__ W,
                      const float* __restrict__ bias)
{
    __shared__ float Xs[128][33];   // padded
    __shared__ float Ws[32][64];    // unpadded (float4 access)

    float* out = (WHICH == 0) ? g_Q : (WHICH == 1) ? g_K : g_V;

    const int h    = blockIdx.y;
    const int row0 = blockIdx.x * 128;
    const int tid  = threadIdx.x;
    const int ridx = tid >> 4;   // 0..15, 8 rows each
    const int cidx = tid & 15;   // 0..15, 4 cols each

    const float* Wh = W + (size_t)h * DD * DKK;

    float acc[8][4];
    #pragma unroll
    for (int r = 0; r < 8; r++)
        #pragma unroll
        for (int c = 0; c < 4; c++) acc[r][c] = 0.0f;

    for (int kt = 0; kt < DD; kt += 32) {
        // Load X tile 128x32 (1024 float4)
        #pragma unroll
        for (int i = 0; i < 4; i++) {
            int idx = tid + i * 256;
            int r = idx >> 3, c4 = idx & 7;
            float4 v = *(const float4*)(X + (size_t)(row0 + r) * DD + kt + c4 * 4);
            Xs[r][c4*4+0] = v.x; Xs[r][c4*4+1] = v.y;
            Xs[r][c4*4+2] = v.z; Xs[r][c4*4+3] = v.w;
        }
        // Load W tile 32x64 (512 float4)
        #pragma unroll
        for (int i = 0; i < 2; i++) {
            int idx = tid + i * 256;
            int kr = idx >> 4, c4 = idx & 15;
            float4 v = *(const float4*)(Wh + (size_t)(kt + kr) * DKK + c4 * 4);
            *(float4*)&Ws[kr][c4*4] = v;
        }
        __syncthreads();

        #pragma unroll
        for (int kk = 0; kk < 32; kk++) {
            float a[8];
            #pragma unroll
            for (int r = 0; r < 8; r++) a[r] = Xs[ridx*8 + r][kk];
            float4 b4 = *(const float4*)&Ws[kk][cidx*4];
            float bb[4] = {b4.x, b4.y, b4.z, b4.w};
            #pragma unroll
            for (int r = 0; r < 8; r++)
                #pragma unroll
                for (int c = 0; c < 4; c++)
                    acc[r][c] = fmaf(a[r], bb[c], acc[r][c]);
        }
        __syncthreads();
    }

    float bvals[4];
    #pragma unroll
    for (int c = 0; c < 4; c++) bvals[c] = bias[h*DKK + cidx*4 + c];

    #pragma unroll
    for (int r = 0; r < 8; r++) {
        int grow = row0 + ridx*8 + r;
        int b = grow / SS, s = grow % SS;
        size_t o = ((size_t)(b*HH + h) * SS + s) * DKK + cidx*4;
        #pragma unroll
        for (int c = 0; c < 4; c++)
            out[o + c] = acc[r][c] + bvals[c];
    }
}

// ---------------------------------------------------------------------------
// Flash attention per (b,h): BR=64 query rows per CTA, BC=64 key cols per tile.
// 256 threads in 16x16 layout, each owning a 4x4 microtile.
// Writes output directly in concat layout g_AO[b, s, h*64 + k].
// ---------------------------------------------------------------------------
__global__ __launch_bounds__(256)
void attn_kernel(const int* __restrict__ mask)
{
    extern __shared__ float sm[];
    float* Qs = sm;               // 64 x 65
    float* Ks = Qs + 64*65;       // 64 x 65
    float* Vs = Ks + 64*65;       // 64 x 65
    float* Ps = Vs + 64*65;       // 64 x 65

    const int bh  = blockIdx.y;          // b*H + h
    const int qr0 = blockIdx.x * 64;
    const int tid = threadIdx.x;
    const int tr  = tid >> 4;            // 0..15 -> 4 query rows each
    const int tc  = tid & 15;            // 0..15 -> 4 key cols each

    const float* Qg = g_Q + (size_t)bh * SS * DKK;
    const float* Kg = g_K + (size_t)bh * SS * DKK;
    const float* Vg = g_V + (size_t)bh * SS * DKK;

    // Load Q tile 64x64 (1024 float4)
    #pragma unroll
    for (int i = 0; i < 4; i++) {
        int idx = tid + i * 256;
        int r = idx >> 4, c4 = idx & 15;
        float4 v = *(const float4*)(Qg + (size_t)(qr0 + r) * DKK + c4 * 4);
        Qs[r*65 + c4*4+0] = v.x; Qs[r*65 + c4*4+1] = v.y;
        Qs[r*65 + c4*4+2] = v.z; Qs[r*65 + c4*4+3] = v.w;
    }

    float m_i[4], l_i[4], o[4][4];
    #pragma unroll
    for (int i = 0; i < 4; i++) {
        m_i[i] = -1e30f; l_i[i] = 0.0f;
        #pragma unroll
        for (int j = 0; j < 4; j++) o[i][j] = 0.0f;
    }

    for (int kt0 = 0; kt0 < SS; kt0 += 64) {
        __syncthreads();  // protect Ks/Vs/Ps from previous iteration (and Qs on iter 0)
        // Load K and V tiles (each 64x64, 1024 float4 total per tile)
        #pragma unroll
        for (int i = 0; i < 4; i++) {
            int idx = tid + i * 256;
            int r = idx >> 4, c4 = idx & 15;
            float4 kv = *(const float4*)(Kg + (size_t)(kt0 + r) * DKK + c4 * 4);
            Ks[r*65 + c4*4+0] = kv.x; Ks[r*65 + c4*4+1] = kv.y;
            Ks[r*65 + c4*4+2] = kv.z; Ks[r*65 + c4*4+3] = kv.w;
            float4 vv = *(const float4*)(Vg + (size_t)(kt0 + r) * DKK + c4 * 4);
            Vs[r*65 + c4*4+0] = vv.x; Vs[r*65 + c4*4+1] = vv.y;
            Vs[r*65 + c4*4+2] = vv.z; Vs[r*65 + c4*4+3] = vv.w;
        }
        __syncthreads();

        // scores = Q . K^T
        float s[4][4];
        #pragma unroll
        for (int i = 0; i < 4; i++)
            #pragma unroll
            for (int j = 0; j < 4; j++) s[i][j] = 0.0f;

        #pragma unroll 8
        for (int k = 0; k < 64; k++) {
            float a[4], bb[4];
            #pragma unroll
            for (int i = 0; i < 4; i++) a[i] = Qs[(tr*4 + i)*65 + k];
            #pragma unroll
            for (int j = 0; j < 4; j++) bb[j] = Ks[(tc*4 + j)*65 + k];
            #pragma unroll
            for (int i = 0; i < 4; i++)
                #pragma unroll
                for (int j = 0; j < 4; j++)
                    s[i][j] = fmaf(a[i], bb[j], s[i][j]);
        }

        // scale + mask (mask==1 -> -1e9, matching reference)
        #pragma unroll
        for (int i = 0; i < 4; i++) {
            int r = qr0 + tr*4 + i;
            #pragma unroll
            for (int j = 0; j < 4; j++) {
                int c = kt0 + tc*4 + j;
                int mval = mask[(size_t)r * SS + c];
                s[i][j] = (mval == 1) ? -1e9f : s[i][j] * 0.125f;
            }
        }

        // online softmax per row (reduce across 16 lanes sharing tr)
        #pragma unroll
        for (int i = 0; i < 4; i++) {
            float mx = s[i][0];
            mx = fmaxf(mx, s[i][1]); mx = fmaxf(mx, s[i][2]); mx = fmaxf(mx, s[i][3]);
            #pragma unroll
            for (int off = 8; off >= 1; off >>= 1)
                mx = fmaxf(mx, __shfl_xor_sync(0xffffffffu, mx, off));
            float mnew = fmaxf(m_i[i], mx);
            float sum = 0.0f;
            #pragma unroll
            for (int j = 0; j < 4; j++) {
                float p = __expf(s[i][j] - mnew);
                s[i][j] = p;
                sum += p;
            }
            #pragma unroll
            for (int off = 8; off >= 1; off >>= 1)
                sum += __shfl_xor_sync(0xffffffffu, sum, off);
            float sc = __expf(m_i[i] - mnew);
            l_i[i] = l_i[i] * sc + sum;
            #pragma unroll
            for (int j = 0; j < 4; j++) o[i][j] *= sc;
            m_i[i] = mnew;
        }

        // write P tile to smem
        #pragma unroll
        for (int i = 0; i < 4; i++)
            #pragma unroll
            for (int j = 0; j < 4; j++)
                Ps[(tr*4 + i)*65 + tc*4 + j] = s[i][j];
        __syncthreads();

        // O += P @ V
        #pragma unroll 8
        for (int t = 0; t < 64; t++) {
            float a[4], bb[4];
            #pragma unroll
            for (int i = 0; i < 4; i++) a[i] = Ps[(tr*4 + i)*65 + t];
            #pragma unroll
            for (int j = 0; j < 4; j++) bb[j] = Vs[t*65 + tc*4 + j];
            #pragma unroll
            for (int i = 0; i < 4; i++)
                #pragma unroll
                for (int j = 0; j < 4; j++)
                    o[i][j] = fmaf(a[i], bb[j], o[i][j]);
        }
    }

    // epilogue: divide by l, write concat layout
    const int b = bh / HH, h = bh % HH;
    #pragma unroll
    for (int i = 0; i < 4; i++) {
        float inv = 1.0f / l_i[i];
        int srow = qr0 + tr*4 + i;
        size_t base = ((size_t)b * SS + srow) * DD + h * DKK + tc*4;
        #pragma unroll
        for (int j = 0; j < 4; j++)
            g_AO[base + j] = o[i][j] * inv;
    }
}

// ---------------------------------------------------------------------------
// Output projection: out[m,n] = sum_k AO[m,k] * Wo[n,k] + bo[n]  (NT GEMM)
// Tile: BM=128, BN=64, BK=32. 256 threads, 8x4 microtile each.
// ---------------------------------------------------------------------------
__global__ __launch_bounds__(256)
void out_proj_kernel(const float* __restrict__ Wo,
                     const float* __restrict__ bo,
                     float* __restrict__ out)
{
    __shared__ float As[128][33];
    __shared__ float Ws[64][33];

    const int n0   = blockIdx.x * 64;
    const int row0 = blockIdx.y * 128;
    const int tid  = threadIdx.x;
    const int ridx = tid >> 4;
    const int cidx = tid & 15;

    float acc[8][4];
    #pragma unroll
    for (int r = 0; r < 8; r++)
        #pragma unroll
        for (int c = 0; c < 4; c++) acc[r][c] = 0.0f;

    for (int kt = 0; kt < DD; kt += 32) {
        // Load AO tile 128x32
        #pragma unroll
        for (int i = 0; i < 4; i++) {
            int idx = tid + i * 256;
            int r = idx >> 3, c4 = idx & 7;
            float4 v = *(const float4*)(g_AO + (size_t)(row0 + r) * DD + kt + c4 * 4);
            As[r][c4*4+0] = v.x; As[r][c4*4+1] = v.y;
            As[r][c4*4+2] = v.z; As[r][c4*4+3] = v.w;
        }
        // Load Wo tile: rows n0..n0+63, cols kt..kt+31
        #pragma unroll
        for (int i = 0; i < 2; i++) {
            int idx = tid + i * 256;
            int r = idx >> 3, c4 = idx & 7;
            float4 v = *(const float4*)(Wo + (size_t)(n0 + r) * DD + kt + c4 * 4);
            Ws[r][c4*4+0] = v.x; Ws[r][c4*4+1] = v.y;
            Ws[r][c4*4+2] = v.z; Ws[r][c4*4+3] = v.w;
        }
        __syncthreads();

        #pragma unroll
        for (int kk = 0; kk < 32; kk++) {
            float a[8], bb[4];
            #pragma unroll
            for (int r = 0; r < 8; r++) a[r] = As[ridx*8 + r][kk];
            #pragma unroll
            for (int c = 0; c < 4; c++) bb[c] = Ws[cidx*4 + c][kk];
            #pragma unroll
            for (int r = 0; r < 8; r++)
                #pragma unroll
                for (int c = 0; c < 4; c++)
                    acc[r][c] = fmaf(a[r], bb[c], acc[r][c]);
        }
        __syncthreads();
    }

    float bvals[4];
    #pragma unroll
    for (int c = 0; c < 4; c++) bvals[c] = bo[n0 + cidx*4 + c];

    #pragma unroll
    for (int r = 0; r < 8; r++) {
        size_t grow = row0 + ridx*8 + r;
        size_t o = grow * DD + n0 + cidx*4;
        #pragma unroll
        for (int c = 0; c < 4; c++)
            out[o + c] = acc[r][c] + bvals[c];
    }
}

// ---------------------------------------------------------------------------
// Launch
// ---------------------------------------------------------------------------
extern "C" void kernel_launch(void* const* d_in, const int* in_sizes, int n_in,
                              void* d_out, int out_size)
{
    const float* ctx  = (const float*)d_in[0];   // [B,S,D]
    const float* val  = (const float*)d_in[1];   // [B,S,D]
    const int*   mask = (const int*)  d_in[2];   // [S,S]
    const float* Wq   = (const float*)d_in[3];
    const float* bq   = (const float*)d_in[4];
    const float* Wk   = (const float*)d_in[5];
    const float* bk   = (const float*)d_in[6];
    const float* Wv   = (const float*)d_in[7];
    const float* bv   = (const float*)d_in[8];
    const float* Wo   = (const float*)d_in[9];
    const float* bo   = (const float*)d_in[10];
    float* out = (float*)d_out;

    (void)in_sizes; (void)n_in; (void)out_size;

    // QKV projections
    dim3 pgrid(MM / 128, HH);
    proj_head_kernel<0><<<pgrid, 256>>>(ctx, Wq, bq);
    proj_head_kernel<1><<<pgrid, 256>>>(ctx, Wk, bk);
    proj_head_kernel<2><<<pgrid, 256>>>(val, Wv, bv);

    // Flash attention
    int attn_smem = 4 * 64 * 65 * (int)sizeof(float);   // 66560 bytes
    cudaFuncSetAttribute(attn_kernel, cudaFuncAttributeMaxDynamicSharedMemorySize, attn_smem);
    dim3 agrid(SS / 64, BB * HH);
    attn_kernel<<<agrid, 256, attn_smem>>>(mask);

    // Output projection
    dim3 ogrid(DD / 64, MM / 128);
    out_proj_kernel<<<ogrid, 256>>>(Wo, bo, out);
}

// round 2
// speedup vs baseline: 2.6833x; 2.6833x over previous
#include <cuda_runtime.h>
#include <math.h>

// Problem constants
#define BB  4
#define SS  2048
#define DD  1024
#define HH  16
#define DKK 64
#define MM  (BB*SS)   // 8192 rows

// Static device scratch
__device__ float    g_Q[(size_t)BB*HH*SS*DKK];   // [B,H,S,DK]
__device__ float    g_K[(size_t)BB*HH*SS*DKK];
__device__ float    g_V[(size_t)BB*HH*SS*DKK];
__device__ float    g_AO[(size_t)BB*SS*DD];      // concat [B,S,D]
__device__ unsigned g_maskbits[SS * (SS/32)];    // bit=1 -> masked

// ---------------------------------------------------------------------------
// helpers
// ---------------------------------------------------------------------------
__device__ __forceinline__ float tf32r(float x) {
    unsigned u;
    asm("cvt.rna.tf32.f32 %0, %1;" : "=r"(u) : "f"(x));
    return __uint_as_float(u);
}
__device__ __forceinline__ float fexp2(float x) {
    float y;
    asm("ex2.approx.ftz.f32 %0, %1;" : "=f"(y) : "f"(x));
    return y;
}
// D(16x8,f32) += A(16x8 tf32, row) * B(8x8 tf32, col)
__device__ __forceinline__ void mma8(float* c, float a0, float a1, float a2, float a3,
                                     float b0, float b1) {
    asm volatile(
        "mma.sync.aligned.m16n8k8.row.col.f32.tf32.tf32.f32 "
        "{%0,%1,%2,%3},{%4,%5,%6,%7},{%8,%9},{%0,%1,%2,%3};"
        : "+f"(c[0]), "+f"(c[1]), "+f"(c[2]), "+f"(c[3])
        : "r"(__float_as_uint(a0)), "r"(__float_as_uint(a1)),
          "r"(__float_as_uint(a2)), "r"(__float_as_uint(a3)),
          "r"(__float_as_uint(b0)), "r"(__float_as_uint(b1)));
}

// ---------------------------------------------------------------------------
// mask -> bitmask (bit set where mask==1)
// ---------------------------------------------------------------------------
__global__ void mask_bits_kernel(const int* __restrict__ mask) {
    int row  = blockIdx.x;
    int warp = threadIdx.x >> 5;
    int lane = threadIdx.x & 31;
    for (int w = warp; w < SS/32; w += 8) {
        int m = mask[(size_t)row * SS + w*32 + lane];
        unsigned bits = __ballot_sync(0xffffffffu, m == 1);
        if (lane == 0) g_maskbits[row * (SS/32) + w] = bits;
    }
}

// ---------------------------------------------------------------------------
// Per-head projection: OUT[b,h,s,n] = X[b,s,:] . W[h,:,n] + bias[h,n]
// BM=128, BN=64, BK=32. 8 warps: wm 0..3 (32 rows), wn 0..1 (32 cols).
// ---------------------------------------------------------------------------
template<int WHICH>
__global__ __launch_bounds__(256)
void proj_mma_kernel(const float* __restrict__ X,
                     const float* __restrict__ W,
                     const float* __restrict__ bias)
{
    __shared__ float Xs[128*36];   // pad 36
    __shared__ float Ws[32*68];    // pad 68

    float* out = (WHICH == 0) ? g_Q : (WHICH == 1) ? g_K : g_V;

    const int h    = blockIdx.y;
    const int row0 = blockIdx.x * 128;
    const int tid  = threadIdx.x;
    const int warp = tid >> 5;
    const int lane = tid & 31;
    const int wm   = warp >> 1;   // 0..3
    const int wn   = warp & 1;    // 0..1
    const int lq   = lane >> 2;   // 0..7
    const int lr   = lane & 3;    // 0..3

    const float* Wh = W + (size_t)h * DD * DKK;

    float acc[2][4][4];
    #pragma unroll
    for (int mt = 0; mt < 2; mt++)
        #pragma unroll
        for (int nt = 0; nt < 4; nt++)
            #pragma unroll
            for (int i = 0; i < 4; i++) acc[mt][nt][i] = 0.0f;

    for (int kt = 0; kt < DD; kt += 32) {
        // X tile 128x32
        #pragma unroll
        for (int i = 0; i < 4; i++) {
            int idx = tid + i*256;
            int r = idx >> 3, c4 = idx & 7;
            float4 v = *(const float4*)(X + (size_t)(row0 + r)*DD + kt + c4*4);
            v.x = tf32r(v.x); v.y = tf32r(v.y); v.z = tf32r(v.z); v.w = tf32r(v.w);
            *(float4*)&Xs[r*36 + c4*4] = v;
        }
        // W tile 32x64 (row=k)
        #pragma unroll
        for (int i = 0; i < 2; i++) {
            int idx = tid + i*256;
            int r = idx >> 4, c4 = idx & 15;
            float4 v = *(const float4*)(Wh + (size_t)(kt + r)*DKK + c4*4);
            v.x = tf32r(v.x); v.y = tf32r(v.y); v.z = tf32r(v.z); v.w = tf32r(v.w);
            *(float4*)&Ws[r*68 + c4*4] = v;
        }
        __syncthreads();

        #pragma unroll
        for (int ks = 0; ks < 4; ks++) {
            int kb = ks*8;
            float a[2][4];
            #pragma unroll
            for (int mt = 0; mt < 2; mt++) {
                int ar = wm*32 + mt*16 + lq;
                a[mt][0] = Xs[ar*36 + kb + lr];
                a[mt][1] = Xs[(ar+8)*36 + kb + lr];
                a[mt][2] = Xs[ar*36 + kb + 4 + lr];
                a[mt][3] = Xs[(ar+8)*36 + kb + 4 + lr];
            }
            #pragma unroll
            for (int nt = 0; nt < 4; nt++) {
                int bc = wn*32 + nt*8 + lq;
                float b0 = Ws[(kb + lr)*68 + bc];
                float b1 = Ws[(kb + 4 + lr)*68 + bc];
                #pragma unroll
                for (int mt = 0; mt < 2; mt++)
                    mma8(acc[mt][nt], a[mt][0], a[mt][1], a[mt][2], a[mt][3], b0, b1);
            }
        }
        __syncthreads();
    }

    // epilogue
    #pragma unroll
    for (int nt = 0; nt < 4; nt++) {
        int col = wn*32 + nt*8 + 2*lr;
        float bv0 = bias[h*DKK + col], bv1 = bias[h*DKK + col + 1];
        #pragma unroll
        for (int mt = 0; mt < 2; mt++) {
            #pragma unroll
            for (int half = 0; half < 2; half++) {
                int grow = row0 + wm*32 + mt*16 + lq + half*8;
                int b = grow / SS, s = grow % SS;
                size_t o = ((size_t)(b*HH + h)*SS + s)*DKK + col;
                float2 v;
                v.x = acc[mt][nt][half*2+0] + bv0;
                v.y = acc[mt][nt][half*2+1] + bv1;
                *(float2*)(out + o) = v;
            }
        }
    }
}

// ---------------------------------------------------------------------------
// Flash attention, BR=128, BC=64. 8 warps, warp wm owns rows wm*16..+15.
// ---------------------------------------------------------------------------
#define PADK 68
__global__ __launch_bounds__(256)
void attn_mma_kernel()
{
    extern __shared__ float sm[];
    float* Qs = sm;                    // 128 x 68
    float* Ks = Qs + 128*PADK;         // 64 x 68
    float* Vs = Ks + 64*PADK;          // 64 x 68
    float* Ps = Vs + 64*PADK;          // 128 x 68

    const int bh  = blockIdx.y;
    const int qr0 = blockIdx.x * 128;
    const int tid = threadIdx.x;
    const int wm  = tid >> 5;          // 0..7
    const int lane= tid & 31;
    const int lq  = lane >> 2;         // 0..7
    const int lr  = lane & 3;          // 0..3

    const float* Qg = g_Q + (size_t)bh * SS * DKK;
    const float* Kg = g_K + (size_t)bh * SS * DKK;
    const float* Vg = g_V + (size_t)bh * SS * DKK;

    // load Q tile (tf32-rounded)
    #pragma unroll
    for (int i = 0; i < 8; i++) {
        int idx = tid + i*256;
        int r = idx >> 4, c4 = idx & 15;
        float4 v = *(const float4*)(Qg + (size_t)(qr0 + r)*DKK + c4*4);
        v.x = tf32r(v.x); v.y = tf32r(v.y); v.z = tf32r(v.z); v.w = tf32r(v.w);
        *(float4*)&Qs[r*PADK + c4*4] = v;
    }

    float o[8][4];
    float m0 = -1e30f, m1 = -1e30f, l0 = 0.0f, l1 = 0.0f;
    #pragma unroll
    for (int nt = 0; nt < 8; nt++)
        #pragma unroll
        for (int i = 0; i < 4; i++) o[nt][i] = 0.0f;

    const int lrow = wm*16 + lq;           // tile-local row (first of pair)
    const int grow0 = qr0 + lrow;
    const int grow1 = grow0 + 8;
    const float SCL = 0.18033688011112042f;   // 0.125 * log2(e)

    for (int kt0 = 0; kt0 < SS; kt0 += 64) {
        __syncthreads();
        // load K,V tiles
        #pragma unroll
        for (int i = 0; i < 4; i++) {
            int idx = tid + i*256;
            int r = idx >> 4, c4 = idx & 15;
            float4 kv = *(const float4*)(Kg + (size_t)(kt0 + r)*DKK + c4*4);
            kv.x = tf32r(kv.x); kv.y = tf32r(kv.y); kv.z = tf32r(kv.z); kv.w = tf32r(kv.w);
            *(float4*)&Ks[r*PADK + c4*4] = kv;
            float4 vv = *(const float4*)(Vg + (size_t)(kt0 + r)*DKK + c4*4);
            vv.x = tf32r(vv.x); vv.y = tf32r(vv.y); vv.z = tf32r(vv.z); vv.w = tf32r(vv.w);
            *(float4*)&Vs[r*PADK + c4*4] = vv;
        }
        __syncthreads();

        // S = Q . K^T
        float s[8][4];
        #pragma unroll
        for (int nt = 0; nt < 8; nt++)
            #pragma unroll
            for (int i = 0; i < 4; i++) s[nt][i] = 0.0f;

        #pragma unroll
        for (int ks = 0; ks < 8; ks++) {
            int kb = ks*8;
            float a0 = Qs[lrow*PADK + kb + lr];
            float a1 = Qs[(lrow+8)*PADK + kb + lr];
            float a2 = Qs[lrow*PADK + kb + 4 + lr];
            float a3 = Qs[(lrow+8)*PADK + kb + 4 + lr];
            #pragma unroll
            for (int nt = 0; nt < 8; nt++) {
                int bc = nt*8 + lq;
                float b0 = Ks[bc*PADK + kb + lr];
                float b1 = Ks[bc*PADK + kb + 4 + lr];
                mma8(s[nt], a0, a1, a2, a3, b0, b1);
            }
        }

        // mask + scale (log2e absorbed)
        unsigned w0a = g_maskbits[grow0*(SS/32) + (kt0>>5)];
        unsigned w0b = g_maskbits[grow0*(SS/32) + (kt0>>5) + 1];
        unsigned w1a = g_maskbits[grow1*(SS/32) + (kt0>>5)];
        unsigned w1b = g_maskbits[grow1*(SS/32) + (kt0>>5) + 1];
        #pragma unroll
        for (int nt = 0; nt < 8; nt++) {
            int c = nt*8 + 2*lr;                 // even, 0..62
            unsigned wr0 = (c < 32) ? w0a : w0b;
            unsigned wr1 = (c < 32) ? w1a : w1b;
            int sh = c & 31;
            s[nt][0] = ((wr0 >> sh)     & 1u) ? -1e9f : s[nt][0]*SCL;
            s[nt][1] = ((wr0 >> (sh+1)) & 1u) ? -1e9f : s[nt][1]*SCL;
            s[nt][2] = ((wr1 >> sh)     & 1u) ? -1e9f : s[nt][2]*SCL;
            s[nt][3] = ((wr1 >> (sh+1)) & 1u) ? -1e9f : s[nt][3]*SCL;
        }

        // online softmax (base-2 domain), rows lrow / lrow+8
        float mx0 = -1e30f, mx1 = -1e30f;
        #pragma unroll
        for (int nt = 0; nt < 8; nt++) {
            mx0 = fmaxf(mx0, fmaxf(s[nt][0], s[nt][1]));
            mx1 = fmaxf(mx1, fmaxf(s[nt][2], s[nt][3]));
        }
        mx0 = fmaxf(mx0, __shfl_xor_sync(0xffffffffu, mx0, 1));
        mx0 = fmaxf(mx0, __shfl_xor_sync(0xffffffffu, mx0, 2));
        mx1 = fmaxf(mx1, __shfl_xor_sync(0xffffffffu, mx1, 1));
        mx1 = fmaxf(mx1, __shfl_xor_sync(0xffffffffu, mx1, 2));
        float mn0 = fmaxf(m0, mx0);
        float mn1 = fmaxf(m1, mx1);
        float sum0 = 0.0f, sum1 = 0.0f;
        #pragma unroll
        for (int nt = 0; nt < 8; nt++) {
            s[nt][0] = fexp2(s[nt][0] - mn0); sum0 += s[nt][0];
            s[nt][1] = fexp2(s[nt][1] - mn0); sum0 += s[nt][1];
            s[nt][2] = fexp2(s[nt][2] - mn1); sum1 += s[nt][2];
            s[nt][3] = fexp2(s[nt][3] - mn1); sum1 += s[nt][3];
        }
        sum0 += __shfl_xor_sync(0xffffffffu, sum0, 1);
        sum0 += __shfl_xor_sync(0xffffffffu, sum0, 2);
        sum1 += __shfl_xor_sync(0xffffffffu, sum1, 1);
        sum1 += __shfl_xor_sync(0xffffffffu, sum1, 2);
        float sc0 = fexp2(m0 - mn0);
        float sc1 = fexp2(m1 - mn1);
        l0 = l0*sc0 + sum0;  m0 = mn0;
        l1 = l1*sc1 + sum1;  m1 = mn1;
        #pragma unroll
        for (int nt = 0; nt < 8; nt++) {
            o[nt][0] *= sc0; o[nt][1] *= sc0;
            o[nt][2] *= sc1; o[nt][3] *= sc1;
        }

        // write P (warp-private rows) as tf32
        #pragma unroll
        for (int nt = 0; nt < 8; nt++) {
            int c = nt*8 + 2*lr;
            float2 p0; p0.x = tf32r(s[nt][0]); p0.y = tf32r(s[nt][1]);
            float2 p1; p1.x = tf32r(s[nt][2]); p1.y = tf32r(s[nt][3]);
            *(float2*)&Ps[lrow*PADK + c]     = p0;
            *(float2*)&Ps[(lrow+8)*PADK + c] = p1;
        }
        __syncwarp();

        // O += P . V
        #pragma unroll
        for (int ks = 0; ks < 8; ks++) {
            int kb = ks*8;
            float a0 = Ps[lrow*PADK + kb + lr];
            float a1 = Ps[(lrow+8)*PADK + kb + lr];
            float a2 = Ps[lrow*PADK + kb + 4 + lr];
            float a3 = Ps[(lrow+8)*PADK + kb + 4 + lr];
            #pragma unroll
            for (int nt = 0; nt < 8; nt++) {
                int bc = nt*8 + lq;
                float b0 = Vs[(kb + lr)*PADK + bc];
                float b1 = Vs[(kb + 4 + lr)*PADK + bc];
                mma8(o[nt], a0, a1, a2, a3, b0, b1);
            }
        }
        __syncwarp();
    }

    // epilogue -> concat layout
    const int b = bh >> 4, h = bh & 15;
    float inv0 = 1.0f / l0, inv1 = 1.0f / l1;
    #pragma unroll
    for (int nt = 0; nt < 8; nt++) {
        int c = nt*8 + 2*lr;
        size_t base0 = ((size_t)(b*SS + grow0))*DD + h*DKK + c;
        size_t base1 = ((size_t)(b*SS + grow1))*DD + h*DKK + c;
        float2 v0; v0.x = o[nt][0]*inv0; v0.y = o[nt][1]*inv0;
        float2 v1; v1.x = o[nt][2]*inv1; v1.y = o[nt][3]*inv1;
        *(float2*)(g_AO + base0) = v0;
        *(float2*)(g_AO + base1) = v1;
    }
}

// ---------------------------------------------------------------------------
// Output projection: out[m,n] = AO[m,:] . Wo[n,:] + bo[n]   (NT)
// BM=128, BN=64, BK=32.
// ---------------------------------------------------------------------------
__global__ __launch_bounds__(256)
void outproj_mma_kernel(const float* __restrict__ Wo,
                        const float* __restrict__ bo,
                        float* __restrict__ out)
{
    __shared__ float As[128*36];
    __shared__ float Ws[64*36];    // [n][k], pad 36

    const int n0   = blockIdx.x * 64;
    const int row0 = blockIdx.y * 128;
    const int tid  = threadIdx.x;
    const int warp = tid >> 5;
    const int lane = tid & 31;
    const int wm   = warp >> 1;
    const int wn   = warp & 1;
    const int lq   = lane >> 2;
    const int lr   = lane & 3;

    float acc[2][4][4];
    #pragma unroll
    for (int mt = 0; mt < 2; mt++)
        #pragma unroll
        for (int nt = 0; nt < 4; nt++)
            #pragma unroll
            for (int i = 0; i < 4; i++) acc[mt][nt][i] = 0.0f;

    for (int kt = 0; kt < DD; kt += 32) {
        #pragma unroll
        for (int i = 0; i < 4; i++) {
            int idx = tid + i*256;
            int r = idx >> 3, c4 = idx & 7;
            float4 v = *(const float4*)(g_AO + (size_t)(row0 + r)*DD + kt + c4*4);
            v.x = tf32r(v.x); v.y = tf32r(v.y); v.z = tf32r(v.z); v.w = tf32r(v.w);
            *(float4*)&As[r*36 + c4*4] = v;
        }
        #pragma unroll
        for (int i = 0; i < 2; i++) {
            int idx = tid + i*256;
            int r = idx >> 3, c4 = idx & 7;
            float4 v = *(const float4*)(Wo + (size_t)(n0 + r)*DD + kt + c4*4);
            v.x = tf32r(v.x); v.y = tf32r(v.y); v.z = tf32r(v.z); v.w = tf32r(v.w);
            *(float4*)&Ws[r*36 + c4*4] = v;
        }
        __syncthreads();

        #pragma unroll
        for (int ks = 0; ks < 4; ks++) {
            int kb = ks*8;
            float a[2][4];
            #pragma unroll
            for (int mt = 0; mt < 2; mt++) {
                int ar = wm*32 + mt*16 + lq;
                a[mt][0] = As[ar*36 + kb + lr];
                a[mt][1] = As[(ar+8)*36 + kb + lr];
                a[mt][2] = As[ar*36 + kb + 4 + lr];
                a[mt][3] = As[(ar+8)*36 + kb + 4 + lr];
            }
            #pragma unroll
            for (int nt = 0; nt < 4; nt++) {
                int nc = wn*32 + nt*8 + lq;
                float b0 = Ws[nc*36 + kb + lr];
                float b1 = Ws[nc*36 + kb + 4 + lr];
                #pragma unroll
                for (int mt = 0; mt < 2; mt++)
                    mma8(acc[mt][nt], a[mt][0], a[mt][1], a[mt][2], a[mt][3], b0, b1);
            }
        }
        __syncthreads();
    }

    #pragma unroll
    for (int nt = 0; nt < 4; nt++) {
        int col = n0 + wn*32 + nt*8 + 2*lr;
        float bv0 = bo[col], bv1 = bo[col+1];
        #pragma unroll
        for (int mt = 0; mt < 2; mt++) {
            #pragma unroll
            for (int half = 0; half < 2; half++) {
                size_t grow = row0 + wm*32 + mt*16 + lq + half*8;
                float2 v;
                v.x = acc[mt][nt][half*2+0] + bv0;
                v.y = acc[mt][nt][half*2+1] + bv1;
                *(float2*)(out + grow*DD + col) = v;
            }
        }
    }
}

// ---------------------------------------------------------------------------
extern "C" void kernel_launch(void* const* d_in, const int* in_sizes, int n_in,
                              void* d_out, int out_size)
{
    const float* ctx  = (const float*)d_in[0];
    const float* val  = (const float*)d_in[1];
    const int*   mask = (const int*)  d_in[2];
    const float* Wq   = (const float*)d_in[3];
    const float* bq   = (const float*)d_in[4];
    const float* Wk   = (const float*)d_in[5];
    const float* bk   = (const float*)d_in[6];
    const float* Wv   = (const float*)d_in[7];
    const float* bv   = (const float*)d_in[8];
    const float* Wo   = (const float*)d_in[9];
    const float* bo   = (const float*)d_in[10];
    float* out = (float*)d_out;
    (void)in_sizes; (void)n_in; (void)out_size;

    // mask -> bits
    mask_bits_kernel<<<SS, 256>>>(mask);

    // QKV projections
    dim3 pgrid(MM / 128, HH);
    proj_mma_kernel<0><<<pgrid, 256>>>(ctx, Wq, bq);
    proj_mma_kernel<1><<<pgrid, 256>>>(ctx, Wk, bk);
    proj_mma_kernel<2><<<pgrid, 256>>>(val, Wv, bv);

    // attention
    int attn_smem = (128 + 64 + 64 + 128) * PADK * (int)sizeof(float);  // 104448
    cudaFuncSetAttribute(attn_mma_kernel, cudaFuncAttributeMaxDynamicSharedMemorySize, attn_smem);
    dim3 agrid(SS / 128, BB * HH);
    attn_mma_kernel<<<agrid, 256, attn_smem>>>();

    // output projection
    dim3 ogrid(DD / 64, MM / 128);
    outproj_mma_kernel<<<ogrid, 256>>>(Wo, bo, out);
}